// round 13
// baseline (speedup 1.0000x reference)
#include <cuda_runtime.h>

#define NCOL 49152          // 16384 points * 3 dims
#define NPTS 16384
#define NBATCH 4
#define NPB 4096
#define RES 64

// ---------------- scratch (static device memory; no allocations) ----------------
__device__ float g_net [128 * NCOL];
__device__ float g_bufA[128 * NCOL];
__device__ float g_bufB[128 * NCOL];
__device__ float g_sums[3 * NBATCH * 4096 * 128];
__device__ float g_cnts[3 * NBATCH * 4096];
__device__ int   g_idx [NBATCH * NPB * 10];

// ---------------- helpers ----------------
union F2u { unsigned long long u; float f[2]; };

__device__ __forceinline__ unsigned long long pk2(float a, float b) {
    unsigned long long r;
    asm("mov.b64 %0, {%1, %2};" : "=l"(r) : "f"(a), "f"(b));
    return r;
}
__device__ __forceinline__ unsigned long long ffma2(unsigned long long a,
                                                    unsigned long long b,
                                                    unsigned long long c) {
    unsigned long long r;
    asm("fma.rn.f32x2 %0, %1, %2, %3;" : "=l"(r) : "l"(a), "l"(b), "l"(c));
    return r;
}
__device__ __forceinline__ float dot3_nofma(float a0, float a1, float a2,
                                            float b0, float b1, float b2) {
    return __fadd_rn(__fadd_rn(__fmul_rn(a0, b0), __fmul_rn(a1, b1)), __fmul_rn(a2, b2));
}

// ---------------- 1) kNN: fp32 scan keeps top-12, double refinement picks true top-10 ----------------
__global__ __launch_bounds__(128)
void knn_kernel(const float* __restrict__ p, int* __restrict__ idx) {
    extern __shared__ float4 sp[];           // 4096 float4 {x,y,z,sq}
    const int b = blockIdx.x >> 5;           // 32 blocks per batch
    const int qbase = (blockIdx.x & 31) * 128;
    const float* pb = p + (size_t)b * NPB * 3;
    for (int i = threadIdx.x; i < NPB; i += 128) {
        float x = pb[i * 3], y = pb[i * 3 + 1], z = pb[i * 3 + 2];
        float sq = __fadd_rn(__fadd_rn(__fmul_rn(x, x), __fmul_rn(y, y)), __fmul_rn(z, z));
        sp[i] = make_float4(x, y, z, sq);
    }
    __syncthreads();
    const int q = qbase + threadIdx.x;
    float4 me = sp[q];
    float bv[12]; int bi[12];
#pragma unroll
    for (int s = 0; s < 12; s++) { bv[s] = -3.4e38f; bi[s] = 0; }
    for (int j = 0; j < NPB; j++) {
        float4 o = sp[j];
        float dot = fmaf(me.z, o.z, fmaf(me.y, o.y, __fmul_rn(me.x, o.x)));
        float nd = __fadd_rn(__fadd_rn(__fmul_rn(2.0f, dot), -me.w), -o.w);
        if (nd > bv[11]) {
            float v = nd; int id = j;
#pragma unroll
            for (int s = 0; s < 12; s++) {
                if (v > bv[s]) {
                    float tv = bv[s]; bv[s] = v; v = tv;
                    int   ti = bi[s]; bi[s] = id; id = ti;
                }
            }
        }
    }
    double mx = (double)me.x, my_ = (double)me.y, mz = (double)me.z;
    double dd[12];
#pragma unroll
    for (int s = 0; s < 12; s++) {
        float4 o = sp[bi[s]];
        double dx = mx - (double)o.x, dy = my_ - (double)o.y, dz = mz - (double)o.z;
        dd[s] = -(dx * dx + dy * dy + dz * dz);
    }
    int* op = idx + (size_t)(b * NPB + q) * 10;
#pragma unroll
    for (int r = 0; r < 10; r++) {
        int best = 0; double bvd = -1e300;
#pragma unroll
        for (int s = 0; s < 12; s++) if (dd[s] > bvd) { bvd = dd[s]; best = s; }
        op[r] = bi[best];
        dd[best] = -1e300;
    }
}

// ---------------- 2) edge features -> vn_lin_lrelu(slope 0) -> mean over k ----------------
__global__ __launch_bounds__(128)
void edge_kernel(const float* __restrict__ p, const int* __restrict__ idx,
                 const float* __restrict__ Wf, const float* __restrict__ Wd,
                 float* __restrict__ out) {
    __shared__ float sF[32 * 91];
    __shared__ float sWf[384], sWd[384];
    const int t = threadIdx.x;
    for (int i = t; i < 384; i += 128) { sWf[i] = Wf[i]; sWd[i] = Wd[i]; }
    const int pbase = blockIdx.x * 32;
    for (int i = t; i < 320; i += 128) {
        int pl = i / 10, k = i - pl * 10;
        int pg = pbase + pl;
        int b = pg >> 12;
        int nb = idx[(size_t)pg * 10 + k];
        const float* pc = p + (size_t)pg * 3;
        const float* pn = p + ((size_t)b * NPB + nb) * 3;
        float cx = pc[0], cy = pc[1], cz = pc[2];
        float nx = pn[0], ny = pn[1], nz = pn[2];
        float* Fk = sF + pl * 91 + k * 9;
        Fk[0] = __fsub_rn(nx, cx); Fk[1] = __fsub_rn(ny, cy); Fk[2] = __fsub_rn(nz, cz);
        Fk[3] = cx;                Fk[4] = cy;                Fk[5] = cz;
        Fk[6] = __fsub_rn(__fmul_rn(ny, cz), __fmul_rn(nz, cy));
        Fk[7] = __fsub_rn(__fmul_rn(nz, cx), __fmul_rn(nx, cz));
        Fk[8] = __fsub_rn(__fmul_rn(nx, cy), __fmul_rn(ny, cx));
    }
    __syncthreads();
    const int pl = t & 31, cg = t >> 5;
    const int pg = pbase + pl;
    const float* Fp = sF + pl * 91;
    for (int cc = 0; cc < 32; cc++) {
        int c = cg * 32 + cc;
        float wf0 = sWf[c * 3], wf1 = sWf[c * 3 + 1], wf2 = sWf[c * 3 + 2];
        float wd0 = sWd[c * 3], wd1 = sWd[c * 3 + 1], wd2 = sWd[c * 3 + 2];
        float a0 = 0.f, a1 = 0.f, a2 = 0.f;
#pragma unroll
        for (int k = 0; k < 10; k++) {
            const float* Fk = Fp + k * 9;
            float f0 = Fk[0], f1 = Fk[1], f2 = Fk[2];
            float f3 = Fk[3], f4 = Fk[4], f5 = Fk[5];
            float f6 = Fk[6], f7 = Fk[7], f8 = Fk[8];
            float xf0 = fmaf(wf2, f6, fmaf(wf1, f3, __fmul_rn(wf0, f0)));
            float xf1 = fmaf(wf2, f7, fmaf(wf1, f4, __fmul_rn(wf0, f1)));
            float xf2 = fmaf(wf2, f8, fmaf(wf1, f5, __fmul_rn(wf0, f2)));
            float xd0 = fmaf(wd2, f6, fmaf(wd1, f3, __fmul_rn(wd0, f0)));
            float xd1 = fmaf(wd2, f7, fmaf(wd1, f4, __fmul_rn(wd0, f1)));
            float xd2 = fmaf(wd2, f8, fmaf(wd1, f5, __fmul_rn(wd0, f2)));
            float dot = dot3_nofma(xf0, xf1, xf2, xd0, xd1, xd2);
            float dsq = dot3_nofma(xd0, xd1, xd2, xd0, xd1, xd2);
            float s0, s1, s2;
            if (dot >= 0.0f) { s0 = xf0; s1 = xf1; s2 = xf2; }
            else {
                float tc = __fdiv_rn(dot, __fadd_rn(dsq, 1e-6f));
                s0 = __fsub_rn(xf0, __fmul_rn(tc, xd0));
                s1 = __fsub_rn(xf1, __fmul_rn(tc, xd1));
                s2 = __fsub_rn(xf2, __fmul_rn(tc, xd2));
            }
            a0 = __fadd_rn(a0, s0); a1 = __fadd_rn(a1, s1); a2 = __fadd_rn(a2, s2);
        }
        float* o = out + (size_t)c * NCOL + (size_t)pg * 3;
        o[0] = __fdiv_rn(a0, 10.0f);
        o[1] = __fdiv_rn(a1, 10.0f);
        o[2] = __fdiv_rn(a2, 10.0f);
    }
}

// ---------------- 3) fused layer chain: 96-col tiles, warp-broadcast X, W in smem ----------------
// smem (floats): sNet[128*96] | sT1[128*96] | sT2[128*96] | sW[128*130]
#define TCOLS 96
#define TILE_F (128 * TCOLS)
#define WSTRIDE 130
#define SW_OFF (3 * TILE_F)

// 512 threads; warp = 4 rowgroups x 8 col-lanes; thread = 2 rows x 12 cols.
// All 4 rowgroups of a warp read identical X addresses -> smem broadcast (free).
// EPI: 0 none | 1 act(x=aux,d=acc) | 2 act(x=acc,d=aux) | 3 acc+aux
template<int M, int K, int EPI>
__device__ __forceinline__ void layer(const float* __restrict__ Wg,
                                      const float* Xs, const float* AuxS, float* Ys,
                                      float* Ws, int t, float slope, float onems) {
    // load W -> smem (row-major M x WSTRIDE)
    const float4* W4 = reinterpret_cast<const float4*>(Wg);
    for (int i = t; i < M * K / 4; i += 512) {
        float4 w = W4[i];
        int m = (i * 4) / K, k = (i * 4) - m * K;
        float* dst = Ws + m * WSTRIDE + k;
        dst[0] = w.x; dst[1] = w.y; dst[2] = w.z; dst[3] = w.w;
    }
    __syncthreads();                    // W ready; prev-layer Ys writes visible

    const int lane = t & 31, warp = t >> 5;
    const int rg = lane >> 3;           // rowgroup 0..3
    const int cg = lane & 7;            // col-lane 0..7 (12 cols each)
    const int row0 = (warp * 4 + rg) * 2;   // 2 rows per thread
    const bool active = row0 < M;
    const int colb = cg * 12;

    unsigned long long acc[2][6];
#pragma unroll
    for (int r = 0; r < 2; r++)
#pragma unroll
        for (int e = 0; e < 6; e++) acc[r][e] = 0ull;

    if (active) {
        const float* xsb = Xs + colb;
        const float* wr0 = Ws + row0 * WSTRIDE;
        const float* wr1 = Ws + (row0 + 1) * WSTRIDE;
#pragma unroll 2
        for (int k0 = 0; k0 < K; k0 += 2) {
            float2 wa = *reinterpret_cast<const float2*>(wr0 + k0);
            float2 wb = *reinterpret_cast<const float2*>(wr1 + k0);
#pragma unroll
            for (int kk = 0; kk < 2; kk++) {
                const float* xr = xsb + (k0 + kk) * TCOLS;
                ulonglong2 x01 = *reinterpret_cast<const ulonglong2*>(xr);
                ulonglong2 x23 = *reinterpret_cast<const ulonglong2*>(xr + 4);
                ulonglong2 x45 = *reinterpret_cast<const ulonglong2*>(xr + 8);
                float w0 = kk ? wa.y : wa.x;
                float w1 = kk ? wb.y : wb.x;
                unsigned long long wp0 = pk2(w0, w0);
                unsigned long long wp1 = pk2(w1, w1);
                acc[0][0] = ffma2(wp0, x01.x, acc[0][0]);
                acc[0][1] = ffma2(wp0, x01.y, acc[0][1]);
                acc[0][2] = ffma2(wp0, x23.x, acc[0][2]);
                acc[0][3] = ffma2(wp0, x23.y, acc[0][3]);
                acc[0][4] = ffma2(wp0, x45.x, acc[0][4]);
                acc[0][5] = ffma2(wp0, x45.y, acc[0][5]);
                acc[1][0] = ffma2(wp1, x01.x, acc[1][0]);
                acc[1][1] = ffma2(wp1, x01.y, acc[1][1]);
                acc[1][2] = ffma2(wp1, x23.x, acc[1][2]);
                acc[1][3] = ffma2(wp1, x23.y, acc[1][3]);
                acc[1][4] = ffma2(wp1, x45.x, acc[1][4]);
                acc[1][5] = ffma2(wp1, x45.y, acc[1][5]);
            }
        }
    }
    __syncthreads();                    // all Xs/AuxS reads done before Ys write may alias

    if (active) {
#pragma unroll
        for (int r = 0; r < 2; r++) {
            int base = (row0 + r) * TCOLS + colb;
            float v[12];
#pragma unroll
            for (int e = 0; e < 6; e++) { F2u u; u.u = acc[r][e]; v[2*e] = u.f[0]; v[2*e+1] = u.f[1]; }
            if (EPI == 1 || EPI == 2 || EPI == 3) {
                float ax[12];
                *reinterpret_cast<float4*>(ax)     = *reinterpret_cast<const float4*>(AuxS + base);
                *reinterpret_cast<float4*>(ax + 4) = *reinterpret_cast<const float4*>(AuxS + base + 4);
                *reinterpret_cast<float4*>(ax + 8) = *reinterpret_cast<const float4*>(AuxS + base + 8);
                if (EPI == 3) {
#pragma unroll
                    for (int e = 0; e < 12; e++) v[e] = __fadd_rn(v[e], ax[e]);
                } else {
#pragma unroll
                    for (int lp = 0; lp < 4; lp++) {
                        float x0, x1, x2, d0, d1, d2;
                        if (EPI == 1) {
                            x0 = ax[lp*3]; x1 = ax[lp*3+1]; x2 = ax[lp*3+2];
                            d0 = v[lp*3];  d1 = v[lp*3+1];  d2 = v[lp*3+2];
                        } else {
                            x0 = v[lp*3];  x1 = v[lp*3+1];  x2 = v[lp*3+2];
                            d0 = ax[lp*3]; d1 = ax[lp*3+1]; d2 = ax[lp*3+2];
                        }
                        float dot = dot3_nofma(x0, x1, x2, d0, d1, d2);
                        float dsq = dot3_nofma(d0, d1, d2, d0, d1, d2);
                        float r0, r1, r2;
                        if (dot >= 0.0f) { r0 = x0; r1 = x1; r2 = x2; }
                        else {
                            float tc = __fdiv_rn(dot, __fadd_rn(dsq, 1e-6f));
                            r0 = __fsub_rn(x0, __fmul_rn(tc, d0));
                            r1 = __fsub_rn(x1, __fmul_rn(tc, d1));
                            r2 = __fsub_rn(x2, __fmul_rn(tc, d2));
                        }
                        v[lp*3]   = __fadd_rn(__fmul_rn(slope, x0), __fmul_rn(onems, r0));
                        v[lp*3+1] = __fadd_rn(__fmul_rn(slope, x1), __fmul_rn(onems, r1));
                        v[lp*3+2] = __fadd_rn(__fmul_rn(slope, x2), __fmul_rn(onems, r2));
                    }
                }
            }
            *reinterpret_cast<float4*>(Ys + base)     = make_float4(v[0], v[1], v[2], v[3]);
            *reinterpret_cast<float4*>(Ys + base + 4) = make_float4(v[4], v[5], v[6], v[7]);
            *reinterpret_cast<float4*>(Ys + base + 8) = make_float4(v[8], v[9], v[10], v[11]);
        }
    }
    __syncthreads();                    // Ys complete before next layer reads it
}

__global__ __launch_bounds__(512, 1)
void mega_kernel(const float* __restrict__ x0,
                 const float* __restrict__ Wfc,
                 const float* __restrict__ Wd0s, const float* __restrict__ W0s,
                 const float* __restrict__ Wd1s, const float* __restrict__ W1s,
                 const float* __restrict__ Ws1d, const float* __restrict__ Ws1f,
                 const float* __restrict__ Ws2d, const float* __restrict__ Ws2f,
                 float* __restrict__ net_out,        // 128 x NCOL
                 float* __restrict__ z2_out) {       // 32 x NCOL
    extern __shared__ float sm[];
    float* sNet = sm;
    float* sT1  = sm + TILE_F;
    float* sT2  = sm + 2 * TILE_F;
    float* sW   = sm + SW_OFF;
    const int t = threadIdx.x;
    const int colbase = blockIdx.x * TCOLS;

    for (int i = t; i < 128 * 24; i += 512) {
        int ch = i / 24, c = (i - ch * 24) * 4;
        *reinterpret_cast<float4*>(sT1 + ch * TCOLS + c) =
            *reinterpret_cast<const float4*>(x0 + (size_t)ch * NCOL + colbase + c);
    }
    __syncthreads();

    layer<128,128,0>(Wfc, sT1, nullptr, sNet, sW, t, 0.f, 1.f);

    for (int i = 0; i < 5; i++) {
        const float* wd0 = Wd0s + (size_t)i * 128 * 128;
        const float* w0  = W0s  + (size_t)i * 128 * 128;
        const float* wd1 = Wd1s + (size_t)i * 128 * 128;
        const float* w1  = W1s  + (size_t)i * 128 * 128;
        layer<128,128,1>(wd0, sNet, sNet, sT1, sW, t, 0.f, 1.f);   // a = act(net, Wd0 net)
        layer<128,128,0>(w0,  sT1,  nullptr, sT2, sW, t, 0.f, 1.f);// tmp = W0 a
        layer<128,128,1>(wd1, sT2,  sT2,  sT1, sW, t, 0.f, 1.f);   // a2 = act(tmp, Wd1 tmp)
        layer<128,128,3>(w1,  sT1,  sNet, sNet, sW, t, 0.f, 1.f);  // net += W1 a2
    }

    layer<64,128,0>(Ws1d, sNet, nullptr, sT1, sW, t, 0.f, 1.f);
    layer<64,128,2>(Ws1f, sNet, sT1, sT2, sW, t, 0.2f, 0.8f);
    layer<32,64,0>(Ws2d, sT2, nullptr, sT1, sW, t, 0.f, 1.f);
    layer<32,64,2>(Ws2f, sT2, sT1, sT1, sW, t, 0.2f, 0.8f);

    for (int i = t; i < 128 * 24; i += 512) {
        int ch = i / 24, c = (i - ch * 24) * 4;
        *reinterpret_cast<float4*>(net_out + (size_t)ch * NCOL + colbase + c) =
            *reinterpret_cast<const float4*>(sNet + ch * TCOLS + c);
    }
    for (int i = t; i < 32 * 24; i += 512) {
        int ch = i / 24, c = (i - ch * 24) * 4;
        *reinterpret_cast<float4*>(z2_out + (size_t)ch * NCOL + colbase + c) =
            *reinterpret_cast<const float4*>(sT1 + ch * TCOLS + c);
    }
}

// ---------------- 4) Wslin + Gram-Schmidt (double) + invariant + scatter ----------------
__device__ __forceinline__ int cell1d_d(float v) {
    double q = (double)v / 1.101 + 0.5;
    if (q >= 1.0) q = 0.99999;
    else if (q < 0.0) q = 0.0;
    return (int)(q * 64.0);
}

__global__ __launch_bounds__(128)
void frame_scatter_kernel(const float* __restrict__ p, const float* __restrict__ z2,
                          const float* __restrict__ net, const float* __restrict__ Wslin,
                          float* __restrict__ sums, float* __restrict__ cnts) {
    __shared__ float sw[64];
    if (threadIdx.x < 64) sw[threadIdx.x] = Wslin[threadIdx.x];
    __syncthreads();
    const int pt = blockIdx.x * 128 + threadIdx.x;
    const int b = pt >> 12;
    float z00 = 0, z01 = 0, z02 = 0, z10 = 0, z11 = 0, z12 = 0;
    for (int ch = 0; ch < 32; ch++) {
        const float* zp = z2 + (size_t)ch * NCOL + (size_t)pt * 3;
        float a0 = zp[0], a1 = zp[1], a2 = zp[2];
        float w0 = sw[ch], w1 = sw[32 + ch];
        z00 = fmaf(w0, a0, z00); z01 = fmaf(w0, a1, z01); z02 = fmaf(w0, a2, z02);
        z10 = fmaf(w1, a0, z10); z11 = fmaf(w1, a1, z11); z12 = fmaf(w1, a2, z12);
    }
    double a0 = z00, a1 = z01, a2 = z02, b0 = z10, b1 = z11, b2 = z12;
    double n1 = sqrt(a0 * a0 + a1 * a1 + a2 * a2) + 1e-6;
    double U1x = a0 / n1, U1y = a1 / n1, U1z = a2 / n1;
    double d21 = b0 * U1x + b1 * U1y + b2 * U1z;
    double v2x = b0 - d21 * U1x, v2y = b1 - d21 * U1y, v2z = b2 - d21 * U1z;
    double n2 = sqrt(v2x * v2x + v2y * v2y + v2z * v2z) + 1e-6;
    double U2x = v2x / n2, U2y = v2y / n2, U2z = v2z / n2;
    double U3x = U1y * U2z - U1z * U2y;
    double U3y = U1z * U2x - U1x * U2z;
    double U3z = U1x * U2y - U1y * U2x;
    float u1x = (float)U1x, u1y = (float)U1y, u1z = (float)U1z;
    float u2x = (float)U2x, u2y = (float)U2y, u2z = (float)U2z;
    float u3x = (float)U3x, u3y = (float)U3y, u3z = (float)U3z;

    float px = p[(size_t)pt * 3], py = p[(size_t)pt * 3 + 1], pz = p[(size_t)pt * 3 + 2];
    int ix = cell1d_d(px), iy = cell1d_d(py), iz = cell1d_d(pz);
    int cxz = ix + 64 * iz, cxy = ix + 64 * iy, cyz = iy + 64 * iz;
    float* s0p = sums + ((size_t)(0 * NBATCH + b) * 4096 + cxz) * 128;
    float* s1p = sums + ((size_t)(1 * NBATCH + b) * 4096 + cxy) * 128;
    float* s2p = sums + ((size_t)(2 * NBATCH + b) * 4096 + cyz) * 128;
    if (blockIdx.y == 0) {
        atomicAdd(&cnts[(0 * NBATCH + b) * 4096 + cxz], 1.0f);
        atomicAdd(&cnts[(1 * NBATCH + b) * 4096 + cxy], 1.0f);
        atomicAdd(&cnts[(2 * NBATCH + b) * 4096 + cyz], 1.0f);
    }

    const int ch0 = blockIdx.y * 32;
    for (int ch = ch0; ch < ch0 + 32; ch++) {
        const float* xp = net + (size_t)ch * NCOL + (size_t)pt * 3;
        float x0 = xp[0], x1 = xp[1], x2 = xp[2];
        float sA = dot3_nofma(x0, x1, x2, u1x, u1y, u1z);
        float sB = dot3_nofma(x0, x1, x2, u2x, u2y, u2z);
        float sC = dot3_nofma(x0, x1, x2, u3x, u3y, u3z);
        float inv = dot3_nofma(sA, sB, sC, sA, sB, sC);
        atomicAdd(s0p + ch, inv);
        atomicAdd(s1p + ch, inv);
        atomicAdd(s2p + ch, inv);
    }
}

// ---------------- 5) mean + transposed write-out ----------------
__global__ __launch_bounds__(256)
void mean_out_kernel(const float* __restrict__ sums, const float* __restrict__ cnts,
                     float* __restrict__ out) {
    extern __shared__ float tile[];
    const int pb = blockIdx.x >> 5;
    const int cb = (blockIdx.x & 31) * 128;
    const float* s = sums + (size_t)pb * 4096 * 128;
    float* cn = tile + 128 * 129;
    for (int i = threadIdx.x; i < 128; i += 256) cn[i] = cnts[pb * 4096 + cb + i];
    for (int i = threadIdx.x; i < 128 * 128; i += 256) {
        int cell = i >> 7, ch = i & 127;
        tile[cell * 129 + ch] = s[(size_t)(cb + cell) * 128 + ch];
    }
    __syncthreads();
    float* o = out + (size_t)pb * 128 * 4096;
    for (int i = threadIdx.x; i < 128 * 128; i += 256) {
        int ch = i >> 7, cell = i & 127;
        o[(size_t)ch * 4096 + cb + cell] = __fdiv_rn(tile[cell * 129 + ch], fmaxf(cn[cell], 1.0f));
    }
}

// ---------------- launch ----------------
static void set_smem(const void* f, int bytes) {
    cudaFuncSetAttribute(f, cudaFuncAttributeMaxDynamicSharedMemorySize, bytes);
}

extern "C" void kernel_launch(void* const* d_in, const int* in_sizes, int n_in,
                              void* d_out, int out_size) {
    const float* p     = (const float*)d_in[0];
    const float* Wcp_f = (const float*)d_in[1];
    const float* Wcp_d = (const float*)d_in[2];
    const float* Wfc   = (const float*)d_in[3];
    const float* Wd0s  = (const float*)d_in[4];
    const float* W0s   = (const float*)d_in[5];
    const float* Wd1s  = (const float*)d_in[6];
    const float* W1s   = (const float*)d_in[7];
    const float* Ws1f  = (const float*)d_in[8];
    const float* Ws1d  = (const float*)d_in[9];
    const float* Ws2f  = (const float*)d_in[10];
    const float* Ws2d  = (const float*)d_in[11];
    const float* Wslin = (const float*)d_in[12];
    float* out = (float*)d_out;

    float *net, *bufA, *bufB, *sums, *cnts; int* idx;
    cudaGetSymbolAddress((void**)&net,  g_net);
    cudaGetSymbolAddress((void**)&bufA, g_bufA);
    cudaGetSymbolAddress((void**)&bufB, g_bufB);
    cudaGetSymbolAddress((void**)&sums, g_sums);
    cudaGetSymbolAddress((void**)&cnts, g_cnts);
    cudaGetSymbolAddress((void**)&idx,  g_idx);

    const int sm_mega = (3 * TILE_F + 128 * WSTRIDE) * 4;   // 214016
    const int sm_knn  = 4096 * 16;                          // 65536
    const int sm_mo   = (128 * 129 + 128) * 4;              // 66560

    set_smem((const void*)knn_kernel, sm_knn);
    set_smem((const void*)mega_kernel, sm_mega);
    set_smem((const void*)mean_out_kernel, sm_mo);

    cudaMemsetAsync(sums, 0, (size_t)3 * NBATCH * 4096 * 128 * sizeof(float));
    cudaMemsetAsync(cnts, 0, (size_t)3 * NBATCH * 4096 * sizeof(float));

    knn_kernel<<<128, 128, sm_knn>>>(p, idx);
    edge_kernel<<<512, 128>>>(p, idx, Wcp_f, Wcp_d, bufA);

    mega_kernel<<<512, 512, sm_mega>>>(bufA, Wfc, Wd0s, W0s, Wd1s, W1s,
                                       Ws1d, Ws1f, Ws2d, Ws2f, net, bufB);

    frame_scatter_kernel<<<dim3(128, 4), 128>>>(p, bufB, net, Wslin, sums, cnts);
    mean_out_kernel<<<384, 256, sm_mo>>>(sums, cnts, out);
}

// round 15
// speedup vs baseline: 1.2352x; 1.2352x over previous
#include <cuda_runtime.h>

#define NCOL 49152          // 16384 points * 3 dims
#define NPTS 16384
#define NBATCH 4
#define NPB 4096
#define RES 64

// ---------------- scratch (static device memory; no allocations) ----------------
__device__ float g_net [128 * NCOL];
__device__ float g_bufA[128 * NCOL];
__device__ float g_bufB[128 * NCOL];
__device__ float g_sums[3 * NBATCH * 4096 * 128];
__device__ float g_cnts[3 * NBATCH * 4096];
__device__ int   g_idx [NBATCH * NPB * 10];

// ---------------- helpers ----------------
union F2u { unsigned long long u; float f[2]; };

__device__ __forceinline__ unsigned long long pk2(float a, float b) {
    unsigned long long r;
    asm("mov.b64 %0, {%1, %2};" : "=l"(r) : "f"(a), "f"(b));
    return r;
}
__device__ __forceinline__ unsigned long long ffma2(unsigned long long a,
                                                    unsigned long long b,
                                                    unsigned long long c) {
    unsigned long long r;
    asm("fma.rn.f32x2 %0, %1, %2, %3;" : "=l"(r) : "l"(a), "l"(b), "l"(c));
    return r;
}
__device__ __forceinline__ float dot3_nofma(float a0, float a1, float a2,
                                            float b0, float b1, float b2) {
    return __fadd_rn(__fadd_rn(__fmul_rn(a0, b0), __fmul_rn(a1, b1)), __fmul_rn(a2, b2));
}

// ---------------- 1) kNN: fp32 scan keeps top-12, double refinement picks true top-10 ----------------
__global__ __launch_bounds__(128)
void knn_kernel(const float* __restrict__ p, int* __restrict__ idx) {
    extern __shared__ float4 sp[];           // 4096 float4 {x,y,z,sq}
    const int b = blockIdx.x >> 5;           // 32 blocks per batch
    const int qbase = (blockIdx.x & 31) * 128;
    const float* pb = p + (size_t)b * NPB * 3;
    for (int i = threadIdx.x; i < NPB; i += 128) {
        float x = pb[i * 3], y = pb[i * 3 + 1], z = pb[i * 3 + 2];
        float sq = __fadd_rn(__fadd_rn(__fmul_rn(x, x), __fmul_rn(y, y)), __fmul_rn(z, z));
        sp[i] = make_float4(x, y, z, sq);
    }
    __syncthreads();
    const int q = qbase + threadIdx.x;
    float4 me = sp[q];
    float bv[12]; int bi[12];
#pragma unroll
    for (int s = 0; s < 12; s++) { bv[s] = -3.4e38f; bi[s] = 0; }
    for (int j = 0; j < NPB; j++) {
        float4 o = sp[j];
        float dot = fmaf(me.z, o.z, fmaf(me.y, o.y, __fmul_rn(me.x, o.x)));
        float nd = __fadd_rn(__fadd_rn(__fmul_rn(2.0f, dot), -me.w), -o.w);
        if (nd > bv[11]) {
            float v = nd; int id = j;
#pragma unroll
            for (int s = 0; s < 12; s++) {
                if (v > bv[s]) {
                    float tv = bv[s]; bv[s] = v; v = tv;
                    int   ti = bi[s]; bi[s] = id; id = ti;
                }
            }
        }
    }
    double mx = (double)me.x, my_ = (double)me.y, mz = (double)me.z;
    double dd[12];
#pragma unroll
    for (int s = 0; s < 12; s++) {
        float4 o = sp[bi[s]];
        double dx = mx - (double)o.x, dy = my_ - (double)o.y, dz = mz - (double)o.z;
        dd[s] = -(dx * dx + dy * dy + dz * dz);
    }
    int* op = idx + (size_t)(b * NPB + q) * 10;
#pragma unroll
    for (int r = 0; r < 10; r++) {
        int best = 0; double bvd = -1e300;
#pragma unroll
        for (int s = 0; s < 12; s++) if (dd[s] > bvd) { bvd = dd[s]; best = s; }
        op[r] = bi[best];
        dd[best] = -1e300;
    }
}

// ---------------- 2) edge features -> vn_lin_lrelu(slope 0) -> mean over k ----------------
__global__ __launch_bounds__(128)
void edge_kernel(const float* __restrict__ p, const int* __restrict__ idx,
                 const float* __restrict__ Wf, const float* __restrict__ Wd,
                 float* __restrict__ out) {
    __shared__ float sF[32 * 91];
    __shared__ float sWf[384], sWd[384];
    const int t = threadIdx.x;
    for (int i = t; i < 384; i += 128) { sWf[i] = Wf[i]; sWd[i] = Wd[i]; }
    const int pbase = blockIdx.x * 32;
    for (int i = t; i < 320; i += 128) {
        int pl = i / 10, k = i - pl * 10;
        int pg = pbase + pl;
        int b = pg >> 12;
        int nb = idx[(size_t)pg * 10 + k];
        const float* pc = p + (size_t)pg * 3;
        const float* pn = p + ((size_t)b * NPB + nb) * 3;
        float cx = pc[0], cy = pc[1], cz = pc[2];
        float nx = pn[0], ny = pn[1], nz = pn[2];
        float* Fk = sF + pl * 91 + k * 9;
        Fk[0] = __fsub_rn(nx, cx); Fk[1] = __fsub_rn(ny, cy); Fk[2] = __fsub_rn(nz, cz);
        Fk[3] = cx;                Fk[4] = cy;                Fk[5] = cz;
        Fk[6] = __fsub_rn(__fmul_rn(ny, cz), __fmul_rn(nz, cy));
        Fk[7] = __fsub_rn(__fmul_rn(nz, cx), __fmul_rn(nx, cz));
        Fk[8] = __fsub_rn(__fmul_rn(nx, cy), __fmul_rn(ny, cx));
    }
    __syncthreads();
    const int pl = t & 31, cg = t >> 5;
    const int pg = pbase + pl;
    const float* Fp = sF + pl * 91;
    for (int cc = 0; cc < 32; cc++) {
        int c = cg * 32 + cc;
        float wf0 = sWf[c * 3], wf1 = sWf[c * 3 + 1], wf2 = sWf[c * 3 + 2];
        float wd0 = sWd[c * 3], wd1 = sWd[c * 3 + 1], wd2 = sWd[c * 3 + 2];
        float a0 = 0.f, a1 = 0.f, a2 = 0.f;
#pragma unroll
        for (int k = 0; k < 10; k++) {
            const float* Fk = Fp + k * 9;
            float f0 = Fk[0], f1 = Fk[1], f2 = Fk[2];
            float f3 = Fk[3], f4 = Fk[4], f5 = Fk[5];
            float f6 = Fk[6], f7 = Fk[7], f8 = Fk[8];
            float xf0 = fmaf(wf2, f6, fmaf(wf1, f3, __fmul_rn(wf0, f0)));
            float xf1 = fmaf(wf2, f7, fmaf(wf1, f4, __fmul_rn(wf0, f1)));
            float xf2 = fmaf(wf2, f8, fmaf(wf1, f5, __fmul_rn(wf0, f2)));
            float xd0 = fmaf(wd2, f6, fmaf(wd1, f3, __fmul_rn(wd0, f0)));
            float xd1 = fmaf(wd2, f7, fmaf(wd1, f4, __fmul_rn(wd0, f1)));
            float xd2 = fmaf(wd2, f8, fmaf(wd1, f5, __fmul_rn(wd0, f2)));
            float dot = dot3_nofma(xf0, xf1, xf2, xd0, xd1, xd2);
            float dsq = dot3_nofma(xd0, xd1, xd2, xd0, xd1, xd2);
            float s0, s1, s2;
            if (dot >= 0.0f) { s0 = xf0; s1 = xf1; s2 = xf2; }
            else {
                float tc = __fdiv_rn(dot, __fadd_rn(dsq, 1e-6f));
                s0 = __fsub_rn(xf0, __fmul_rn(tc, xd0));
                s1 = __fsub_rn(xf1, __fmul_rn(tc, xd1));
                s2 = __fsub_rn(xf2, __fmul_rn(tc, xd2));
            }
            a0 = __fadd_rn(a0, s0); a1 = __fadd_rn(a1, s1); a2 = __fadd_rn(a2, s2);
        }
        float* o = out + (size_t)c * NCOL + (size_t)pg * 3;
        o[0] = __fdiv_rn(a0, 10.0f);
        o[1] = __fdiv_rn(a1, 10.0f);
        o[2] = __fdiv_rn(a2, 10.0f);
    }
}

// ---------------- 3) fused layer chain — R9 layout + reduced issue count ----------------
// smem (floats): sNet[128*96] | sT1[128*96] | sT2[128*96] | sW[128*130]
#define TILE_F (128 * 96)
#define WSTRIDE 130
#define SW_OFF (3 * TILE_F)

// 256 threads: 32 channel-groups (TC=M/32 rows) x 8 col-groups (12 cols).
// X loaded pre-packed (ulonglong2), W as float2 per 2k. Same addresses/order as R9.
// EPI: 0 none | 1 act(x=aux,d=acc) | 2 act(x=acc,d=aux) | 3 acc+aux
template<int M, int K, int EPI>
__device__ __forceinline__ void layer(const float* __restrict__ Wg,
                                      const float* Xs, const float* AuxS, float* Ys,
                                      float* Ws, int t, float slope, float onems) {
    constexpr int TC = M / 32;
    // load W -> smem (row-major M x WSTRIDE)
    const float4* W4 = reinterpret_cast<const float4*>(Wg);
    for (int i = t; i < M * K / 4; i += 256) {
        float4 w = W4[i];
        int m = (i * 4) / K, k = (i * 4) - m * K;
        float* dst = Ws + m * WSTRIDE + k;
        dst[0] = w.x; dst[1] = w.y; dst[2] = w.z; dst[3] = w.w;
    }
    __syncthreads();                    // W ready; prev-layer writes visible

    const int ptg = t & 7, chg = t >> 3;
    unsigned long long acc[TC][6];
#pragma unroll
    for (int c = 0; c < TC; c++)
#pragma unroll
        for (int e = 0; e < 6; e++) acc[c][e] = 0ull;

    const float* xsb = Xs + ptg * 12;
    const float* wrb = Ws + chg * TC * WSTRIDE;
#pragma unroll 2
    for (int k0 = 0; k0 < K; k0 += 2) {
        float2 wv[TC];
#pragma unroll
        for (int c = 0; c < TC; c++)
            wv[c] = *reinterpret_cast<const float2*>(wrb + c * WSTRIDE + k0);
#pragma unroll
        for (int kk = 0; kk < 2; kk++) {
            const float* xr = xsb + (k0 + kk) * 96;
            ulonglong2 x01 = *reinterpret_cast<const ulonglong2*>(xr);
            ulonglong2 x23 = *reinterpret_cast<const ulonglong2*>(xr + 4);
            ulonglong2 x45 = *reinterpret_cast<const ulonglong2*>(xr + 8);
#pragma unroll
            for (int c = 0; c < TC; c++) {
                float w = kk ? wv[c].y : wv[c].x;
                unsigned long long wp = pk2(w, w);
                acc[c][0] = ffma2(wp, x01.x, acc[c][0]);
                acc[c][1] = ffma2(wp, x01.y, acc[c][1]);
                acc[c][2] = ffma2(wp, x23.x, acc[c][2]);
                acc[c][3] = ffma2(wp, x23.y, acc[c][3]);
                acc[c][4] = ffma2(wp, x45.x, acc[c][4]);
                acc[c][5] = ffma2(wp, x45.y, acc[c][5]);
            }
        }
    }

#pragma unroll
    for (int c = 0; c < TC; c++) {
        int row = chg * TC + c;
        int base = row * 96 + ptg * 12;
        float v[12];
#pragma unroll
        for (int e = 0; e < 6; e++) { F2u u; u.u = acc[c][e]; v[2*e] = u.f[0]; v[2*e+1] = u.f[1]; }
        if (EPI == 1 || EPI == 2 || EPI == 3) {
            float ax[12];
#pragma unroll
            for (int e = 0; e < 12; e++) ax[e] = AuxS[base + e];
            if (EPI == 3) {
#pragma unroll
                for (int e = 0; e < 12; e++) v[e] = __fadd_rn(v[e], ax[e]);
            } else {
#pragma unroll
                for (int lp = 0; lp < 4; lp++) {
                    float x0, x1, x2, d0, d1, d2;
                    if (EPI == 1) {
                        x0 = ax[lp*3]; x1 = ax[lp*3+1]; x2 = ax[lp*3+2];
                        d0 = v[lp*3];  d1 = v[lp*3+1];  d2 = v[lp*3+2];
                    } else {
                        x0 = v[lp*3];  x1 = v[lp*3+1];  x2 = v[lp*3+2];
                        d0 = ax[lp*3]; d1 = ax[lp*3+1]; d2 = ax[lp*3+2];
                    }
                    float dot = dot3_nofma(x0, x1, x2, d0, d1, d2);
                    float dsq = dot3_nofma(d0, d1, d2, d0, d1, d2);
                    float r0, r1, r2;
                    if (dot >= 0.0f) { r0 = x0; r1 = x1; r2 = x2; }
                    else {
                        float tc = __fdiv_rn(dot, __fadd_rn(dsq, 1e-6f));
                        r0 = __fsub_rn(x0, __fmul_rn(tc, d0));
                        r1 = __fsub_rn(x1, __fmul_rn(tc, d1));
                        r2 = __fsub_rn(x2, __fmul_rn(tc, d2));
                    }
                    v[lp*3]   = __fadd_rn(__fmul_rn(slope, x0), __fmul_rn(onems, r0));
                    v[lp*3+1] = __fadd_rn(__fmul_rn(slope, x1), __fmul_rn(onems, r1));
                    v[lp*3+2] = __fadd_rn(__fmul_rn(slope, x2), __fmul_rn(onems, r2));
                }
            }
        }
#pragma unroll
        for (int e = 0; e < 12; e++) Ys[base + e] = v[e];
    }
    __syncthreads();                    // dst complete before next layer reuses buffers
}

__global__ __launch_bounds__(256, 1)
void mega_kernel(const float* __restrict__ x0,
                 const float* __restrict__ Wfc,
                 const float* __restrict__ Wd0s, const float* __restrict__ W0s,
                 const float* __restrict__ Wd1s, const float* __restrict__ W1s,
                 const float* __restrict__ Ws1d, const float* __restrict__ Ws1f,
                 const float* __restrict__ Ws2d, const float* __restrict__ Ws2f,
                 float* __restrict__ net_out,        // 128 x NCOL
                 float* __restrict__ z2_out) {       // 32 x NCOL
    extern __shared__ float sm[];
    float* sNet = sm;
    float* sT1  = sm + TILE_F;
    float* sT2  = sm + 2 * TILE_F;
    float* sW   = sm + SW_OFF;
    const int t = threadIdx.x;
    const int colbase = blockIdx.x * 96;

    for (int i = t; i < 128 * 24; i += 256) {
        int ch = i / 24, c = (i - ch * 24) * 4;
        *reinterpret_cast<float4*>(sT1 + ch * 96 + c) =
            *reinterpret_cast<const float4*>(x0 + (size_t)ch * NCOL + colbase + c);
    }
    __syncthreads();

    layer<128,128,0>(Wfc, sT1, nullptr, sNet, sW, t, 0.f, 1.f);

    for (int i = 0; i < 5; i++) {
        const float* wd0 = Wd0s + (size_t)i * 128 * 128;
        const float* w0  = W0s  + (size_t)i * 128 * 128;
        const float* wd1 = Wd1s + (size_t)i * 128 * 128;
        const float* w1  = W1s  + (size_t)i * 128 * 128;
        layer<128,128,1>(wd0, sNet, sNet, sT1, sW, t, 0.f, 1.f);   // a = act(net, Wd0 net)
        layer<128,128,0>(w0,  sT1,  nullptr, sT2, sW, t, 0.f, 1.f);// tmp = W0 a
        layer<128,128,1>(wd1, sT2,  sT2,  sT1, sW, t, 0.f, 1.f);   // a2 = act(tmp, Wd1 tmp)
        layer<128,128,3>(w1,  sT1,  sNet, sNet, sW, t, 0.f, 1.f);  // net += W1 a2
    }

    layer<64,128,0>(Ws1d, sNet, nullptr, sT1, sW, t, 0.f, 1.f);
    layer<64,128,2>(Ws1f, sNet, sT1, sT2, sW, t, 0.2f, 0.8f);
    layer<32,64,0>(Ws2d, sT2, nullptr, sT1, sW, t, 0.f, 1.f);
    layer<32,64,2>(Ws2f, sT2, sT1, sT1, sW, t, 0.2f, 0.8f);

    for (int i = t; i < 128 * 24; i += 256) {
        int ch = i / 24, c = (i - ch * 24) * 4;
        *reinterpret_cast<float4*>(net_out + (size_t)ch * NCOL + colbase + c) =
            *reinterpret_cast<const float4*>(sNet + ch * 96 + c);
    }
    for (int i = t; i < 32 * 24; i += 256) {
        int ch = i / 24, c = (i - ch * 24) * 4;
        *reinterpret_cast<float4*>(z2_out + (size_t)ch * NCOL + colbase + c) =
            *reinterpret_cast<const float4*>(sT1 + ch * 96 + c);
    }
}

// ---------------- 4) Wslin + Gram-Schmidt (double) + invariant + scatter ----------------
__device__ __forceinline__ int cell1d_d(float v) {
    double q = (double)v / 1.101 + 0.5;
    if (q >= 1.0) q = 0.99999;
    else if (q < 0.0) q = 0.0;
    return (int)(q * 64.0);
}

__global__ __launch_bounds__(128)
void frame_scatter_kernel(const float* __restrict__ p, const float* __restrict__ z2,
                          const float* __restrict__ net, const float* __restrict__ Wslin,
                          float* __restrict__ sums, float* __restrict__ cnts) {
    __shared__ float sw[64];
    if (threadIdx.x < 64) sw[threadIdx.x] = Wslin[threadIdx.x];
    __syncthreads();
    const int pt = blockIdx.x * 128 + threadIdx.x;
    const int b = pt >> 12;
    float z00 = 0, z01 = 0, z02 = 0, z10 = 0, z11 = 0, z12 = 0;
    for (int ch = 0; ch < 32; ch++) {
        const float* zp = z2 + (size_t)ch * NCOL + (size_t)pt * 3;
        float a0 = zp[0], a1 = zp[1], a2 = zp[2];
        float w0 = sw[ch], w1 = sw[32 + ch];
        z00 = fmaf(w0, a0, z00); z01 = fmaf(w0, a1, z01); z02 = fmaf(w0, a2, z02);
        z10 = fmaf(w1, a0, z10); z11 = fmaf(w1, a1, z11); z12 = fmaf(w1, a2, z12);
    }
    double a0 = z00, a1 = z01, a2 = z02, b0 = z10, b1 = z11, b2 = z12;
    double n1 = sqrt(a0 * a0 + a1 * a1 + a2 * a2) + 1e-6;
    double U1x = a0 / n1, U1y = a1 / n1, U1z = a2 / n1;
    double d21 = b0 * U1x + b1 * U1y + b2 * U1z;
    double v2x = b0 - d21 * U1x, v2y = b1 - d21 * U1y, v2z = b2 - d21 * U1z;
    double n2 = sqrt(v2x * v2x + v2y * v2y + v2z * v2z) + 1e-6;
    double U2x = v2x / n2, U2y = v2y / n2, U2z = v2z / n2;
    double U3x = U1y * U2z - U1z * U2y;
    double U3y = U1z * U2x - U1x * U2z;
    double U3z = U1x * U2y - U1y * U2x;
    float u1x = (float)U1x, u1y = (float)U1y, u1z = (float)U1z;
    float u2x = (float)U2x, u2y = (float)U2y, u2z = (float)U2z;
    float u3x = (float)U3x, u3y = (float)U3y, u3z = (float)U3z;

    float px = p[(size_t)pt * 3], py = p[(size_t)pt * 3 + 1], pz = p[(size_t)pt * 3 + 2];
    int ix = cell1d_d(px), iy = cell1d_d(py), iz = cell1d_d(pz);
    int cxz = ix + 64 * iz, cxy = ix + 64 * iy, cyz = iy + 64 * iz;
    float* s0p = sums + ((size_t)(0 * NBATCH + b) * 4096 + cxz) * 128;
    float* s1p = sums + ((size_t)(1 * NBATCH + b) * 4096 + cxy) * 128;
    float* s2p = sums + ((size_t)(2 * NBATCH + b) * 4096 + cyz) * 128;
    atomicAdd(&cnts[(0 * NBATCH + b) * 4096 + cxz], 1.0f);
    atomicAdd(&cnts[(1 * NBATCH + b) * 4096 + cxy], 1.0f);
    atomicAdd(&cnts[(2 * NBATCH + b) * 4096 + cyz], 1.0f);

    for (int ch = 0; ch < 128; ch++) {
        const float* xp = net + (size_t)ch * NCOL + (size_t)pt * 3;
        float x0 = xp[0], x1 = xp[1], x2 = xp[2];
        float sA = dot3_nofma(x0, x1, x2, u1x, u1y, u1z);
        float sB = dot3_nofma(x0, x1, x2, u2x, u2y, u2z);
        float sC = dot3_nofma(x0, x1, x2, u3x, u3y, u3z);
        float inv = dot3_nofma(sA, sB, sC, sA, sB, sC);
        atomicAdd(s0p + ch, inv);
        atomicAdd(s1p + ch, inv);
        atomicAdd(s2p + ch, inv);
    }
}

// ---------------- 5) mean + transposed write-out ----------------
__global__ __launch_bounds__(256)
void mean_out_kernel(const float* __restrict__ sums, const float* __restrict__ cnts,
                     float* __restrict__ out) {
    extern __shared__ float tile[];
    const int pb = blockIdx.x >> 5;
    const int cb = (blockIdx.x & 31) * 128;
    const float* s = sums + (size_t)pb * 4096 * 128;
    float* cn = tile + 128 * 129;
    for (int i = threadIdx.x; i < 128; i += 256) cn[i] = cnts[pb * 4096 + cb + i];
    for (int i = threadIdx.x; i < 128 * 128; i += 256) {
        int cell = i >> 7, ch = i & 127;
        tile[cell * 129 + ch] = s[(size_t)(cb + cell) * 128 + ch];
    }
    __syncthreads();
    float* o = out + (size_t)pb * 128 * 4096;
    for (int i = threadIdx.x; i < 128 * 128; i += 256) {
        int ch = i >> 7, cell = i & 127;
        o[(size_t)ch * 4096 + cb + cell] = __fdiv_rn(tile[cell * 129 + ch], fmaxf(cn[cell], 1.0f));
    }
}

// ---------------- launch ----------------
static void set_smem(const void* f, int bytes) {
    cudaFuncSetAttribute(f, cudaFuncAttributeMaxDynamicSharedMemorySize, bytes);
}

extern "C" void kernel_launch(void* const* d_in, const int* in_sizes, int n_in,
                              void* d_out, int out_size) {
    const float* p     = (const float*)d_in[0];
    const float* Wcp_f = (const float*)d_in[1];
    const float* Wcp_d = (const float*)d_in[2];
    const float* Wfc   = (const float*)d_in[3];
    const float* Wd0s  = (const float*)d_in[4];
    const float* W0s   = (const float*)d_in[5];
    const float* Wd1s  = (const float*)d_in[6];
    const float* W1s   = (const float*)d_in[7];
    const float* Ws1f  = (const float*)d_in[8];
    const float* Ws1d  = (const float*)d_in[9];
    const float* Ws2f  = (const float*)d_in[10];
    const float* Ws2d  = (const float*)d_in[11];
    const float* Wslin = (const float*)d_in[12];
    float* out = (float*)d_out;

    float *net, *bufA, *bufB, *sums, *cnts; int* idx;
    cudaGetSymbolAddress((void**)&net,  g_net);
    cudaGetSymbolAddress((void**)&bufA, g_bufA);
    cudaGetSymbolAddress((void**)&bufB, g_bufB);
    cudaGetSymbolAddress((void**)&sums, g_sums);
    cudaGetSymbolAddress((void**)&cnts, g_cnts);
    cudaGetSymbolAddress((void**)&idx,  g_idx);

    const int sm_mega = (3 * TILE_F + 128 * WSTRIDE) * 4;   // 214016
    const int sm_knn  = 4096 * 16;                          // 65536
    const int sm_mo   = (128 * 129 + 128) * 4;              // 66560

    set_smem((const void*)knn_kernel, sm_knn);
    set_smem((const void*)mega_kernel, sm_mega);
    set_smem((const void*)mean_out_kernel, sm_mo);

    cudaMemsetAsync(sums, 0, (size_t)3 * NBATCH * 4096 * 128 * sizeof(float));
    cudaMemsetAsync(cnts, 0, (size_t)3 * NBATCH * 4096 * sizeof(float));

    knn_kernel<<<128, 128, sm_knn>>>(p, idx);
    edge_kernel<<<512, 128>>>(p, idx, Wcp_f, Wcp_d, bufA);

    mega_kernel<<<512, 256, sm_mega>>>(bufA, Wfc, Wd0s, W0s, Wd1s, W1s,
                                       Ws1d, Ws1f, Ws2d, Ws2f, net, bufB);

    frame_scatter_kernel<<<128, 128>>>(p, bufB, net, Wslin, sums, cnts);
    mean_out_kernel<<<384, 256, sm_mo>>>(sums, cnts, out);
}

// round 16
// speedup vs baseline: 1.2895x; 1.0439x over previous
#include <cuda_runtime.h>

#define NCOL 49152          // 16384 points * 3 dims
#define NPTS 16384
#define NBATCH 4
#define NPB 4096
#define RES 64

// ---------------- scratch (static device memory; no allocations) ----------------
__device__ float g_net [128 * NCOL];
__device__ float g_bufA[128 * NCOL];
__device__ float g_bufB[128 * NCOL];
__device__ float g_sums[3 * NBATCH * 4096 * 128];
__device__ float g_cnts[3 * NBATCH * 4096];
__device__ int   g_idx [NBATCH * NPB * 10];

// ---------------- helpers ----------------
union F2u { unsigned long long u; float f[2]; };

__device__ __forceinline__ unsigned long long pk2(float a, float b) {
    unsigned long long r;
    asm("mov.b64 %0, {%1, %2};" : "=l"(r) : "f"(a), "f"(b));
    return r;
}
__device__ __forceinline__ unsigned long long ffma2(unsigned long long a,
                                                    unsigned long long b,
                                                    unsigned long long c) {
    unsigned long long r;
    asm("fma.rn.f32x2 %0, %1, %2, %3;" : "=l"(r) : "l"(a), "l"(b), "l"(c));
    return r;
}
__device__ __forceinline__ float dot3_nofma(float a0, float a1, float a2,
                                            float b0, float b1, float b2) {
    return __fadd_rn(__fadd_rn(__fmul_rn(a0, b0), __fmul_rn(a1, b1)), __fmul_rn(a2, b2));
}

// ---------------- 1) kNN: fp32 scan keeps top-12, double refinement picks true top-10 ----------------
__global__ __launch_bounds__(128)
void knn_kernel(const float* __restrict__ p, int* __restrict__ idx) {
    extern __shared__ float4 sp[];           // 4096 float4 {x,y,z,sq}
    const int b = blockIdx.x >> 5;           // 32 blocks per batch
    const int qbase = (blockIdx.x & 31) * 128;
    const float* pb = p + (size_t)b * NPB * 3;
    for (int i = threadIdx.x; i < NPB; i += 128) {
        float x = pb[i * 3], y = pb[i * 3 + 1], z = pb[i * 3 + 2];
        float sq = __fadd_rn(__fadd_rn(__fmul_rn(x, x), __fmul_rn(y, y)), __fmul_rn(z, z));
        sp[i] = make_float4(x, y, z, sq);
    }
    __syncthreads();
    const int q = qbase + threadIdx.x;
    float4 me = sp[q];
    float bv[12]; int bi[12];
#pragma unroll
    for (int s = 0; s < 12; s++) { bv[s] = -3.4e38f; bi[s] = 0; }
    for (int j = 0; j < NPB; j++) {
        float4 o = sp[j];
        float dot = fmaf(me.z, o.z, fmaf(me.y, o.y, __fmul_rn(me.x, o.x)));
        float nd = __fadd_rn(__fadd_rn(__fmul_rn(2.0f, dot), -me.w), -o.w);
        if (nd > bv[11]) {
            float v = nd; int id = j;
#pragma unroll
            for (int s = 0; s < 12; s++) {
                if (v > bv[s]) {
                    float tv = bv[s]; bv[s] = v; v = tv;
                    int   ti = bi[s]; bi[s] = id; id = ti;
                }
            }
        }
    }
    double mx = (double)me.x, my_ = (double)me.y, mz = (double)me.z;
    double dd[12];
#pragma unroll
    for (int s = 0; s < 12; s++) {
        float4 o = sp[bi[s]];
        double dx = mx - (double)o.x, dy = my_ - (double)o.y, dz = mz - (double)o.z;
        dd[s] = -(dx * dx + dy * dy + dz * dz);
    }
    int* op = idx + (size_t)(b * NPB + q) * 10;
#pragma unroll
    for (int r = 0; r < 10; r++) {
        int best = 0; double bvd = -1e300;
#pragma unroll
        for (int s = 0; s < 12; s++) if (dd[s] > bvd) { bvd = dd[s]; best = s; }
        op[r] = bi[best];
        dd[best] = -1e300;
    }
}

// ---------------- 2) edge features -> vn_lin_lrelu(slope 0) -> mean over k ----------------
__global__ __launch_bounds__(128)
void edge_kernel(const float* __restrict__ p, const int* __restrict__ idx,
                 const float* __restrict__ Wf, const float* __restrict__ Wd,
                 float* __restrict__ out) {
    __shared__ float sF[32 * 91];
    __shared__ float sWf[384], sWd[384];
    const int t = threadIdx.x;
    for (int i = t; i < 384; i += 128) { sWf[i] = Wf[i]; sWd[i] = Wd[i]; }
    const int pbase = blockIdx.x * 32;
    for (int i = t; i < 320; i += 128) {
        int pl = i / 10, k = i - pl * 10;
        int pg = pbase + pl;
        int b = pg >> 12;
        int nb = idx[(size_t)pg * 10 + k];
        const float* pc = p + (size_t)pg * 3;
        const float* pn = p + ((size_t)b * NPB + nb) * 3;
        float cx = pc[0], cy = pc[1], cz = pc[2];
        float nx = pn[0], ny = pn[1], nz = pn[2];
        float* Fk = sF + pl * 91 + k * 9;
        Fk[0] = __fsub_rn(nx, cx); Fk[1] = __fsub_rn(ny, cy); Fk[2] = __fsub_rn(nz, cz);
        Fk[3] = cx;                Fk[4] = cy;                Fk[5] = cz;
        Fk[6] = __fsub_rn(__fmul_rn(ny, cz), __fmul_rn(nz, cy));
        Fk[7] = __fsub_rn(__fmul_rn(nz, cx), __fmul_rn(nx, cz));
        Fk[8] = __fsub_rn(__fmul_rn(nx, cy), __fmul_rn(ny, cx));
    }
    __syncthreads();
    const int pl = t & 31, cg = t >> 5;
    const int pg = pbase + pl;
    const float* Fp = sF + pl * 91;
    for (int cc = 0; cc < 32; cc++) {
        int c = cg * 32 + cc;
        float wf0 = sWf[c * 3], wf1 = sWf[c * 3 + 1], wf2 = sWf[c * 3 + 2];
        float wd0 = sWd[c * 3], wd1 = sWd[c * 3 + 1], wd2 = sWd[c * 3 + 2];
        float a0 = 0.f, a1 = 0.f, a2 = 0.f;
#pragma unroll
        for (int k = 0; k < 10; k++) {
            const float* Fk = Fp + k * 9;
            float f0 = Fk[0], f1 = Fk[1], f2 = Fk[2];
            float f3 = Fk[3], f4 = Fk[4], f5 = Fk[5];
            float f6 = Fk[6], f7 = Fk[7], f8 = Fk[8];
            float xf0 = fmaf(wf2, f6, fmaf(wf1, f3, __fmul_rn(wf0, f0)));
            float xf1 = fmaf(wf2, f7, fmaf(wf1, f4, __fmul_rn(wf0, f1)));
            float xf2 = fmaf(wf2, f8, fmaf(wf1, f5, __fmul_rn(wf0, f2)));
            float xd0 = fmaf(wd2, f6, fmaf(wd1, f3, __fmul_rn(wd0, f0)));
            float xd1 = fmaf(wd2, f7, fmaf(wd1, f4, __fmul_rn(wd0, f1)));
            float xd2 = fmaf(wd2, f8, fmaf(wd1, f5, __fmul_rn(wd0, f2)));
            float dot = dot3_nofma(xf0, xf1, xf2, xd0, xd1, xd2);
            float dsq = dot3_nofma(xd0, xd1, xd2, xd0, xd1, xd2);
            float s0, s1, s2;
            if (dot >= 0.0f) { s0 = xf0; s1 = xf1; s2 = xf2; }
            else {
                float tc = __fdiv_rn(dot, __fadd_rn(dsq, 1e-6f));
                s0 = __fsub_rn(xf0, __fmul_rn(tc, xd0));
                s1 = __fsub_rn(xf1, __fmul_rn(tc, xd1));
                s2 = __fsub_rn(xf2, __fmul_rn(tc, xd2));
            }
            a0 = __fadd_rn(a0, s0); a1 = __fadd_rn(a1, s1); a2 = __fadd_rn(a2, s2);
        }
        float* o = out + (size_t)c * NCOL + (size_t)pg * 3;
        o[0] = __fdiv_rn(a0, 10.0f);
        o[1] = __fdiv_rn(a1, 10.0f);
        o[2] = __fdiv_rn(a2, 10.0f);
    }
}

// ---------------- 3) fused layer chain: 2-tile in-place GEMM, 48-col tiles, occ 2 ----------------
// smem (floats): sNet[128*48] | sT1[128*48] | sW[128*130]   (115712 B)
#define TCOLS 48
#define TILE_F (128 * TCOLS)
#define WSTRIDE 130
#define SW_OFF (2 * TILE_F)

// 256 threads: 32 channel-groups (TC=M/32 rows) x 8 col-groups (6 cols each).
// Accumulators live in registers; Ys may alias Xs/AuxS (sync separates read/write).
// EPI: 0 none | 1 act(x=aux,d=acc) | 2 act(x=acc,d=aux) | 3 acc+aux
template<int M, int K, int EPI>
__device__ __forceinline__ void layer(const float* __restrict__ Wg,
                                      const float* Xs, const float* AuxS, float* Ys,
                                      float* Ws, int t, float slope, float onems) {
    constexpr int TC = M / 32;
    // load W -> smem (row-major M x WSTRIDE)
    const float4* W4 = reinterpret_cast<const float4*>(Wg);
    for (int i = t; i < M * K / 4; i += 256) {
        float4 w = W4[i];
        int m = (i * 4) / K, k = (i * 4) - m * K;
        float* dst = Ws + m * WSTRIDE + k;
        dst[0] = w.x; dst[1] = w.y; dst[2] = w.z; dst[3] = w.w;
    }
    __syncthreads();                    // W ready; prev-layer writes visible

    const int ptg = t & 7, chg = t >> 3;
    const int colb = ptg * 6;
    unsigned long long acc[TC][3];
#pragma unroll
    for (int c = 0; c < TC; c++)
#pragma unroll
        for (int e = 0; e < 3; e++) acc[c][e] = 0ull;

    const float* xsb = Xs + colb;
    const float* wrb = Ws + chg * TC * WSTRIDE;
#pragma unroll 2
    for (int k0 = 0; k0 < K; k0 += 2) {
        float2 wv[TC];
#pragma unroll
        for (int c = 0; c < TC; c++)
            wv[c] = *reinterpret_cast<const float2*>(wrb + c * WSTRIDE + k0);
#pragma unroll
        for (int kk = 0; kk < 2; kk++) {
            const float* xr = xsb + (k0 + kk) * TCOLS;
            unsigned long long x0 = *reinterpret_cast<const unsigned long long*>(xr);
            unsigned long long x1 = *reinterpret_cast<const unsigned long long*>(xr + 2);
            unsigned long long x2 = *reinterpret_cast<const unsigned long long*>(xr + 4);
#pragma unroll
            for (int c = 0; c < TC; c++) {
                float w = kk ? wv[c].y : wv[c].x;
                unsigned long long wp = pk2(w, w);
                acc[c][0] = ffma2(wp, x0, acc[c][0]);
                acc[c][1] = ffma2(wp, x1, acc[c][1]);
                acc[c][2] = ffma2(wp, x2, acc[c][2]);
            }
        }
    }
    __syncthreads();                    // ALL reads of Xs/AuxS-as-src done; Ys may alias

    {
#pragma unroll
        for (int c = 0; c < TC; c++) {
            int row = chg * TC + c;
            int base = row * TCOLS + colb;
            float v[6];
#pragma unroll
            for (int e = 0; e < 3; e++) { F2u u; u.u = acc[c][e]; v[2*e] = u.f[0]; v[2*e+1] = u.f[1]; }
            if (EPI == 1 || EPI == 2 || EPI == 3) {
                float ax[6];
                *reinterpret_cast<float2*>(ax)     = *reinterpret_cast<const float2*>(AuxS + base);
                *reinterpret_cast<float2*>(ax + 2) = *reinterpret_cast<const float2*>(AuxS + base + 2);
                *reinterpret_cast<float2*>(ax + 4) = *reinterpret_cast<const float2*>(AuxS + base + 4);
                if (EPI == 3) {
#pragma unroll
                    for (int e = 0; e < 6; e++) v[e] = __fadd_rn(v[e], ax[e]);
                } else {
#pragma unroll
                    for (int lp = 0; lp < 2; lp++) {
                        float x0, x1, x2, d0, d1, d2;
                        if (EPI == 1) {
                            x0 = ax[lp*3]; x1 = ax[lp*3+1]; x2 = ax[lp*3+2];
                            d0 = v[lp*3];  d1 = v[lp*3+1];  d2 = v[lp*3+2];
                        } else {
                            x0 = v[lp*3];  x1 = v[lp*3+1];  x2 = v[lp*3+2];
                            d0 = ax[lp*3]; d1 = ax[lp*3+1]; d2 = ax[lp*3+2];
                        }
                        float dot = dot3_nofma(x0, x1, x2, d0, d1, d2);
                        float dsq = dot3_nofma(d0, d1, d2, d0, d1, d2);
                        float r0, r1, r2;
                        if (dot >= 0.0f) { r0 = x0; r1 = x1; r2 = x2; }
                        else {
                            float tc = __fdiv_rn(dot, __fadd_rn(dsq, 1e-6f));
                            r0 = __fsub_rn(x0, __fmul_rn(tc, d0));
                            r1 = __fsub_rn(x1, __fmul_rn(tc, d1));
                            r2 = __fsub_rn(x2, __fmul_rn(tc, d2));
                        }
                        v[lp*3]   = __fadd_rn(__fmul_rn(slope, x0), __fmul_rn(onems, r0));
                        v[lp*3+1] = __fadd_rn(__fmul_rn(slope, x1), __fmul_rn(onems, r1));
                        v[lp*3+2] = __fadd_rn(__fmul_rn(slope, x2), __fmul_rn(onems, r2));
                    }
                }
            }
            *reinterpret_cast<float2*>(Ys + base)     = make_float2(v[0], v[1]);
            *reinterpret_cast<float2*>(Ys + base + 2) = make_float2(v[2], v[3]);
            *reinterpret_cast<float2*>(Ys + base + 4) = make_float2(v[4], v[5]);
        }
    }
    __syncthreads();                    // Ys complete before next layer reads it
}

__global__ __launch_bounds__(256, 2)
void mega_kernel(const float* __restrict__ x0,
                 const float* __restrict__ Wfc,
                 const float* __restrict__ Wd0s, const float* __restrict__ W0s,
                 const float* __restrict__ Wd1s, const float* __restrict__ W1s,
                 const float* __restrict__ Ws1d, const float* __restrict__ Ws1f,
                 const float* __restrict__ Ws2d, const float* __restrict__ Ws2f,
                 float* __restrict__ net_out,        // 128 x NCOL
                 float* __restrict__ z2_out) {       // 32 x NCOL
    extern __shared__ float sm[];
    float* sNet = sm;
    float* sT1  = sm + TILE_F;
    float* sW   = sm + SW_OFF;
    const int t = threadIdx.x;
    const int colbase = blockIdx.x * TCOLS;

    for (int i = t; i < 128 * 12; i += 256) {
        int ch = i / 12, c = (i - ch * 12) * 4;
        *reinterpret_cast<float4*>(sT1 + ch * TCOLS + c) =
            *reinterpret_cast<const float4*>(x0 + (size_t)ch * NCOL + colbase + c);
    }
    __syncthreads();

    layer<128,128,0>(Wfc, sT1, nullptr, sNet, sW, t, 0.f, 1.f);

    for (int i = 0; i < 5; i++) {
        const float* wd0 = Wd0s + (size_t)i * 128 * 128;
        const float* w0  = W0s  + (size_t)i * 128 * 128;
        const float* wd1 = Wd1s + (size_t)i * 128 * 128;
        const float* w1  = W1s  + (size_t)i * 128 * 128;
        layer<128,128,1>(wd0, sNet, sNet, sT1, sW, t, 0.f, 1.f);   // a = act(net, Wd0 net)
        layer<128,128,0>(w0,  sT1,  nullptr, sT1, sW, t, 0.f, 1.f);// tmp = W0 a (in-place)
        layer<128,128,1>(wd1, sT1,  sT1,  sT1, sW, t, 0.f, 1.f);   // a2 = act(tmp, Wd1 tmp) (in-place)
        layer<128,128,3>(w1,  sT1,  sNet, sNet, sW, t, 0.f, 1.f);  // net += W1 a2
    }

    // flush net to gmem (sNet gets reused below)
    for (int i = t; i < 128 * 12; i += 256) {
        int ch = i / 12, c = (i - ch * 12) * 4;
        *reinterpret_cast<float4*>(net_out + (size_t)ch * NCOL + colbase + c) =
            *reinterpret_cast<const float4*>(sNet + ch * TCOLS + c);
    }
    // std_feature: d1 -> sT1; z -> sNet (rows 0-63); d2 -> sT1 (rows 0-31); z2 -> sT1
    layer<64,128,0>(Ws1d, sNet, nullptr, sT1, sW, t, 0.f, 1.f);
    layer<64,128,2>(Ws1f, sNet, sT1, sNet, sW, t, 0.2f, 0.8f);
    layer<32,64,0>(Ws2d, sNet, nullptr, sT1, sW, t, 0.f, 1.f);
    layer<32,64,2>(Ws2f, sNet, sT1, sT1, sW, t, 0.2f, 0.8f);

    for (int i = t; i < 32 * 12; i += 256) {
        int ch = i / 12, c = (i - ch * 12) * 4;
        *reinterpret_cast<float4*>(z2_out + (size_t)ch * NCOL + colbase + c) =
            *reinterpret_cast<const float4*>(sT1 + ch * TCOLS + c);
    }
}

// ---------------- 4) Wslin + Gram-Schmidt (double) + invariant + scatter ----------------
__device__ __forceinline__ int cell1d_d(float v) {
    double q = (double)v / 1.101 + 0.5;
    if (q >= 1.0) q = 0.99999;
    else if (q < 0.0) q = 0.0;
    return (int)(q * 64.0);
}

__global__ __launch_bounds__(128)
void frame_scatter_kernel(const float* __restrict__ p, const float* __restrict__ z2,
                          const float* __restrict__ net, const float* __restrict__ Wslin,
                          float* __restrict__ sums, float* __restrict__ cnts) {
    __shared__ float sw[64];
    if (threadIdx.x < 64) sw[threadIdx.x] = Wslin[threadIdx.x];
    __syncthreads();
    const int pt = blockIdx.x * 128 + threadIdx.x;
    const int b = pt >> 12;
    float z00 = 0, z01 = 0, z02 = 0, z10 = 0, z11 = 0, z12 = 0;
    for (int ch = 0; ch < 32; ch++) {
        const float* zp = z2 + (size_t)ch * NCOL + (size_t)pt * 3;
        float a0 = zp[0], a1 = zp[1], a2 = zp[2];
        float w0 = sw[ch], w1 = sw[32 + ch];
        z00 = fmaf(w0, a0, z00); z01 = fmaf(w0, a1, z01); z02 = fmaf(w0, a2, z02);
        z10 = fmaf(w1, a0, z10); z11 = fmaf(w1, a1, z11); z12 = fmaf(w1, a2, z12);
    }
    double a0 = z00, a1 = z01, a2 = z02, b0 = z10, b1 = z11, b2 = z12;
    double n1 = sqrt(a0 * a0 + a1 * a1 + a2 * a2) + 1e-6;
    double U1x = a0 / n1, U1y = a1 / n1, U1z = a2 / n1;
    double d21 = b0 * U1x + b1 * U1y + b2 * U1z;
    double v2x = b0 - d21 * U1x, v2y = b1 - d21 * U1y, v2z = b2 - d21 * U1z;
    double n2 = sqrt(v2x * v2x + v2y * v2y + v2z * v2z) + 1e-6;
    double U2x = v2x / n2, U2y = v2y / n2, U2z = v2z / n2;
    double U3x = U1y * U2z - U1z * U2y;
    double U3y = U1z * U2x - U1x * U2z;
    double U3z = U1x * U2y - U1y * U2x;
    float u1x = (float)U1x, u1y = (float)U1y, u1z = (float)U1z;
    float u2x = (float)U2x, u2y = (float)U2y, u2z = (float)U2z;
    float u3x = (float)U3x, u3y = (float)U3y, u3z = (float)U3z;

    float px = p[(size_t)pt * 3], py = p[(size_t)pt * 3 + 1], pz = p[(size_t)pt * 3 + 2];
    int ix = cell1d_d(px), iy = cell1d_d(py), iz = cell1d_d(pz);
    int cxz = ix + 64 * iz, cxy = ix + 64 * iy, cyz = iy + 64 * iz;
    float* s0p = sums + ((size_t)(0 * NBATCH + b) * 4096 + cxz) * 128;
    float* s1p = sums + ((size_t)(1 * NBATCH + b) * 4096 + cxy) * 128;
    float* s2p = sums + ((size_t)(2 * NBATCH + b) * 4096 + cyz) * 128;
    atomicAdd(&cnts[(0 * NBATCH + b) * 4096 + cxz], 1.0f);
    atomicAdd(&cnts[(1 * NBATCH + b) * 4096 + cxy], 1.0f);
    atomicAdd(&cnts[(2 * NBATCH + b) * 4096 + cyz], 1.0f);

    for (int ch = 0; ch < 128; ch++) {
        const float* xp = net + (size_t)ch * NCOL + (size_t)pt * 3;
        float x0 = xp[0], x1 = xp[1], x2 = xp[2];
        float sA = dot3_nofma(x0, x1, x2, u1x, u1y, u1z);
        float sB = dot3_nofma(x0, x1, x2, u2x, u2y, u2z);
        float sC = dot3_nofma(x0, x1, x2, u3x, u3y, u3z);
        float inv = dot3_nofma(sA, sB, sC, sA, sB, sC);
        atomicAdd(s0p + ch, inv);
        atomicAdd(s1p + ch, inv);
        atomicAdd(s2p + ch, inv);
    }
}

// ---------------- 5) mean + transposed write-out ----------------
__global__ __launch_bounds__(256)
void mean_out_kernel(const float* __restrict__ sums, const float* __restrict__ cnts,
                     float* __restrict__ out) {
    extern __shared__ float tile[];
    const int pb = blockIdx.x >> 5;
    const int cb = (blockIdx.x & 31) * 128;
    const float* s = sums + (size_t)pb * 4096 * 128;
    float* cn = tile + 128 * 129;
    for (int i = threadIdx.x; i < 128; i += 256) cn[i] = cnts[pb * 4096 + cb + i];
    for (int i = threadIdx.x; i < 128 * 128; i += 256) {
        int cell = i >> 7, ch = i & 127;
        tile[cell * 129 + ch] = s[(size_t)(cb + cell) * 128 + ch];
    }
    __syncthreads();
    float* o = out + (size_t)pb * 128 * 4096;
    for (int i = threadIdx.x; i < 128 * 128; i += 256) {
        int ch = i >> 7, cell = i & 127;
        o[(size_t)ch * 4096 + cb + cell] = __fdiv_rn(tile[cell * 129 + ch], fmaxf(cn[cell], 1.0f));
    }
}

// ---------------- launch ----------------
static void set_smem(const void* f, int bytes) {
    cudaFuncSetAttribute(f, cudaFuncAttributeMaxDynamicSharedMemorySize, bytes);
}

extern "C" void kernel_launch(void* const* d_in, const int* in_sizes, int n_in,
                              void* d_out, int out_size) {
    const float* p     = (const float*)d_in[0];
    const float* Wcp_f = (const float*)d_in[1];
    const float* Wcp_d = (const float*)d_in[2];
    const float* Wfc   = (const float*)d_in[3];
    const float* Wd0s  = (const float*)d_in[4];
    const float* W0s   = (const float*)d_in[5];
    const float* Wd1s  = (const float*)d_in[6];
    const float* W1s   = (const float*)d_in[7];
    const float* Ws1f  = (const float*)d_in[8];
    const float* Ws1d  = (const float*)d_in[9];
    const float* Ws2f  = (const float*)d_in[10];
    const float* Ws2d  = (const float*)d_in[11];
    const float* Wslin = (const float*)d_in[12];
    float* out = (float*)d_out;

    float *net, *bufA, *bufB, *sums, *cnts; int* idx;
    cudaGetSymbolAddress((void**)&net,  g_net);
    cudaGetSymbolAddress((void**)&bufA, g_bufA);
    cudaGetSymbolAddress((void**)&bufB, g_bufB);
    cudaGetSymbolAddress((void**)&sums, g_sums);
    cudaGetSymbolAddress((void**)&cnts, g_cnts);
    cudaGetSymbolAddress((void**)&idx,  g_idx);

    const int sm_mega = (2 * TILE_F + 128 * WSTRIDE) * 4;   // 115712
    const int sm_knn  = 4096 * 16;                          // 65536
    const int sm_mo   = (128 * 129 + 128) * 4;              // 66560

    set_smem((const void*)knn_kernel, sm_knn);
    set_smem((const void*)mega_kernel, sm_mega);
    set_smem((const void*)mean_out_kernel, sm_mo);

    cudaMemsetAsync(sums, 0, (size_t)3 * NBATCH * 4096 * 128 * sizeof(float));
    cudaMemsetAsync(cnts, 0, (size_t)3 * NBATCH * 4096 * sizeof(float));

    knn_kernel<<<128, 128, sm_knn>>>(p, idx);
    edge_kernel<<<512, 128>>>(p, idx, Wcp_f, Wcp_d, bufA);

    mega_kernel<<<1024, 256, sm_mega>>>(bufA, Wfc, Wd0s, W0s, Wd1s, W1s,
                                        Ws1d, Ws1f, Ws2d, Ws2f, net, bufB);

    frame_scatter_kernel<<<128, 128>>>(p, bufB, net, Wslin, sums, cnts);
    mean_out_kernel<<<384, 256, sm_mo>>>(sums, cnts, out);
}